// round 7
// baseline (speedup 1.0000x reference)
#include <cuda_runtime.h>
#include <cuda_bf16.h>
#include <math.h>

#define D 4096
#define H 2
#define HD (D / H)     // 2048
#define E 8192

// Scratch (device globals — no allocations allowed). Fully overwritten every run.
__device__ float g_x[2 * D];        // embeddings / attention input
__device__ float g_qkv[2 * 3 * D];  // packed qkv
__device__ float g_o[2 * D];        // attention output (pre out-proj)
__device__ float g_x1[2 * D];       // after residual 1
__device__ float g_h[2 * D];        // ffn hidden
__device__ float g_x2[2 * D];       // after residual 2
__device__ float g_g[2 * E];        // expert hidden

// ---------------------------------------------------------------------------
// Stage 0: per-task embeddings  x[l][i] = relu(ray[l]*emb_w[i] + emb_b[i])
// ---------------------------------------------------------------------------
__global__ void k_embed(const float* __restrict__ ray,
                        const float* __restrict__ w1, const float* __restrict__ b1,
                        const float* __restrict__ w2, const float* __restrict__ b2) {
    int i = blockIdx.x * blockDim.x + threadIdx.x;
    if (i < D) {
        float r0 = __ldg(ray + 0);
        float r1 = __ldg(ray + 1);
        g_x[i]     = fmaxf(r0 * w1[i] + b1[i], 0.0f);
        g_x[D + i] = fmaxf(r1 * w2[i] + b2[i], 0.0f);
    }
}

// ---------------------------------------------------------------------------
// Warp-per-row persistent 2-row GEMV (K = 4096 fixed).
//  - Each WARP owns whole output rows (warp-strided): no __syncthreads in the
//    loop, shuffle reduction paid once per 512B/lane (8x less often than the
//    block-per-row version).
//  - Rotating register double-buffer (4 float4 cur + 4 float4 nxt) over the
//    8 groups of the row; the LAST group prefetches group 0 of the warp's
//    NEXT row, so weight LDGs stay in flight across the reduction/epilogue.
//  - x vectors cached in shared memory (32 KB/block), keeping registers for
//    the weight pipeline.
// ---------------------------------------------------------------------------
template <bool RELU, bool RESID>
__global__ void __launch_bounds__(256, 4)
k_gemv_w(const float* __restrict__ W,
         const float* __restrict__ b,
         const float* __restrict__ xin,     // [2][D]
         const float* __restrict__ resid,   // [2][N] or null
         float* __restrict__ out,           // [2][N]
         int N) {
    __shared__ float4 sx0[D / 4];           // 16 KB
    __shared__ float4 sx1[D / 4];           // 16 KB

    const int tid  = threadIdx.x;
    const int warp = tid >> 5, lane = tid & 31;

    const float4* __restrict__ x0 = reinterpret_cast<const float4*>(xin);
    const float4* __restrict__ x1 = reinterpret_cast<const float4*>(xin + D);
#pragma unroll
    for (int t = 0; t < 4; ++t) {
        sx0[t * 256 + tid] = x0[t * 256 + tid];
        sx1[t * 256 + tid] = x1[t * 256 + tid];
    }
    __syncthreads();

    const int stride = gridDim.x * 8;       // total warps
    int j = blockIdx.x * 8 + warp;
    if (j >= N) return;

    // Prologue: group 0 of first row.
    float4 cur[4], nxt[4];
    {
        const float4* __restrict__ wr = reinterpret_cast<const float4*>(W + (size_t)j * D);
#pragma unroll
        for (int t = 0; t < 4; ++t) cur[t] = wr[t * 32 + lane];
    }

    for (; j < N; j += stride) {
        const float4* __restrict__ wr = reinterpret_cast<const float4*>(W + (size_t)j * D);
        const int jn = j + stride;

        float a0 = 0.0f, a1 = 0.0f;
#pragma unroll
        for (int g = 0; g < 8; ++g) {
            // Prefetch: next group of this row, or group 0 of next row.
            if (g < 7) {
#pragma unroll
                for (int t = 0; t < 4; ++t) nxt[t] = wr[(g + 1) * 128 + t * 32 + lane];
            } else if (jn < N) {
                const float4* __restrict__ wr2 =
                    reinterpret_cast<const float4*>(W + (size_t)jn * D);
#pragma unroll
                for (int t = 0; t < 4; ++t) nxt[t] = wr2[t * 32 + lane];
            }
            // Consume current group.
#pragma unroll
            for (int t = 0; t < 4; ++t) {
                const int idx = g * 128 + t * 32 + lane;
                float4 xa = sx0[idx];
                float4 xb = sx1[idx];
                a0 += cur[t].x * xa.x + cur[t].y * xa.y + cur[t].z * xa.z + cur[t].w * xa.w;
                a1 += cur[t].x * xb.x + cur[t].y * xb.y + cur[t].z * xb.z + cur[t].w * xb.w;
            }
#pragma unroll
            for (int t = 0; t < 4; ++t) cur[t] = nxt[t];
        }

        // Warp-only reduction (no barriers anywhere in the loop).
#pragma unroll
        for (int off = 16; off; off >>= 1) {
            a0 += __shfl_xor_sync(0xFFFFFFFFu, a0, off);
            a1 += __shfl_xor_sync(0xFFFFFFFFu, a1, off);
        }
        if (lane == 0) {
            float bb = b ? b[j] : 0.0f;
            float r0 = a0 + bb;
            float r1 = a1 + bb;
            if (RESID) { r0 += resid[j]; r1 += resid[N + j]; }
            if (RELU)  { r0 = fmaxf(r0, 0.0f); r1 = fmaxf(r1, 0.0f); }
            out[j]     = r0;
            out[N + j] = r1;
        }
    }
}

// ---------------------------------------------------------------------------
// Stage 2: multi-head attention on the 2-token sequence (tiny; one block).
// ---------------------------------------------------------------------------
__global__ void k_attn() {
    __shared__ float s_scores[8];  // index: h*4 + l*2 + m
    __shared__ float s_attn[8];
    const int tid = threadIdx.x;          // 256 threads = 8 warps
    const int warp = tid >> 5, lane = tid & 31;

    // one warp per (h, l, m) combination
    const int h = warp >> 2, l = (warp >> 1) & 1, m = warp & 1;
    const float* __restrict__ q = g_qkv + l * 3 * D + h * HD;
    const float* __restrict__ k = g_qkv + m * 3 * D + D + h * HD;
    float acc = 0.0f;
#pragma unroll 4
    for (int i = lane; i < HD; i += 32) acc += q[i] * k[i];
#pragma unroll
    for (int off = 16; off; off >>= 1) acc += __shfl_xor_sync(0xFFFFFFFFu, acc, off);
    if (lane == 0) s_scores[warp] = acc * rsqrtf((float)HD);
    __syncthreads();

    if (tid < 4) {  // (h, l) pairs: softmax over m (2 elements)
        int hh = tid >> 1, ll = tid & 1;
        float s0v = s_scores[hh * 4 + ll * 2 + 0];
        float s1v = s_scores[hh * 4 + ll * 2 + 1];
        float mx = fmaxf(s0v, s1v);
        float e0 = __expf(s0v - mx), e1 = __expf(s1v - mx);
        float inv = 1.0f / (e0 + e1);
        s_attn[hh * 4 + ll * 2 + 0] = e0 * inv;
        s_attn[hh * 4 + ll * 2 + 1] = e1 * inv;
    }
    __syncthreads();

    for (int i = tid; i < 2 * D; i += blockDim.x) {
        int l2 = i / D;
        int d = i - l2 * D;
        int h2 = d / HD;
        float v0 = g_qkv[0 * 3 * D + 2 * D + d];
        float v1 = g_qkv[1 * 3 * D + 2 * D + d];
        g_o[i] = s_attn[h2 * 4 + l2 * 2 + 0] * v0 +
                 s_attn[h2 * 4 + l2 * 2 + 1] * v1;
    }
}

// ---------------------------------------------------------------------------
// Stage 7: out = 0.5 * dot(g0 + g1, exp_w2) + exp_b2
// ---------------------------------------------------------------------------
__global__ void k_final(const float* __restrict__ w2,
                        const float* __restrict__ b2,
                        float* __restrict__ out) {
    __shared__ float red[32];
    float acc = 0.0f;
    for (int i = threadIdx.x; i < E; i += blockDim.x)
        acc += (g_g[i] + g_g[E + i]) * w2[i];
#pragma unroll
    for (int off = 16; off; off >>= 1) acc += __shfl_xor_sync(0xFFFFFFFFu, acc, off);
    const int warp = threadIdx.x >> 5, lane = threadIdx.x & 31;
    if (lane == 0) red[warp] = acc;
    __syncthreads();
    if (threadIdx.x == 0) {
        float s = 0.0f;
        const int nw = blockDim.x >> 5;
        for (int w = 0; w < nw; ++w) s += red[w];
        out[0] = 0.5f * s + b2[0];
    }
}

// ---------------------------------------------------------------------------
extern "C" void kernel_launch(void* const* d_in, const int* in_sizes, int n_in,
                              void* d_out, int out_size) {
    const float* ray        = (const float*)d_in[0];
    const float* emb1_w     = (const float*)d_in[1];
    const float* emb1_b     = (const float*)d_in[2];
    const float* emb2_w     = (const float*)d_in[3];
    const float* emb2_b     = (const float*)d_in[4];
    const float* attn_in_w  = (const float*)d_in[5];
    const float* attn_in_b  = (const float*)d_in[6];
    const float* attn_out_w = (const float*)d_in[7];
    const float* attn_out_b = (const float*)d_in[8];
    const float* ffn1_w     = (const float*)d_in[9];
    const float* ffn1_b     = (const float*)d_in[10];
    const float* ffn2_w     = (const float*)d_in[11];
    const float* ffn2_b     = (const float*)d_in[12];
    const float* exp_w1     = (const float*)d_in[13];
    const float* exp_b1     = (const float*)d_in[14];
    const float* exp_w2     = (const float*)d_in[15];
    const float* exp_b2     = (const float*)d_in[16];
    // d_in[17] = idx (always 0, single expert) — unused
    float* out = (float*)d_out;

    float *px, *pqkv, *po, *px1, *ph, *px2, *pg;
    cudaGetSymbolAddress((void**)&px,   g_x);
    cudaGetSymbolAddress((void**)&pqkv, g_qkv);
    cudaGetSymbolAddress((void**)&po,   g_o);
    cudaGetSymbolAddress((void**)&px1,  g_x1);
    cudaGetSymbolAddress((void**)&ph,   g_h);
    cudaGetSymbolAddress((void**)&px2,  g_x2);
    cudaGetSymbolAddress((void**)&pg,   g_g);

    const int GRID = 148 * 4;   // persistent, 4 blocks/SM, 8 warps/block

    // 0: embeddings -> g_x [2][D]
    k_embed<<<(D + 255) / 256, 256>>>(ray, emb1_w, emb1_b, emb2_w, emb2_b);

    // 1: qkv = x @ attn_in_w^T + b  -> g_qkv [2][3D]   (201 MB of weights)
    k_gemv_w<false, false><<<GRID, 256>>>(attn_in_w, attn_in_b, px, nullptr, pqkv, 3 * D);

    // 2: attention -> g_o [2][D]
    k_attn<<<1, 256>>>();

    // 3: x1 = x + o @ attn_out_w^T + b
    k_gemv_w<false, true><<<GRID, 256>>>(attn_out_w, attn_out_b, po, px, px1, D);

    // 4: h = relu(x1 @ ffn1_w^T + b1)
    k_gemv_w<true, false><<<GRID, 256>>>(ffn1_w, ffn1_b, px1, nullptr, ph, D);

    // 5: x2 = x1 + h @ ffn2_w^T + b2
    k_gemv_w<false, true><<<GRID, 256>>>(ffn2_w, ffn2_b, ph, px1, px2, D);

    // 6: g = relu(x2 @ exp_w1^T + b1)  -> [2][E]   (134 MB of weights)
    k_gemv_w<true, false><<<GRID, 256>>>(exp_w1, exp_b1, px2, nullptr, pg, E);

    // 7: out = mean over seq of (g @ exp_w2^T + b2)
    k_final<<<1, 1024>>>(exp_w2, exp_b2, out);
}

// round 8
// speedup vs baseline: 2.9653x; 2.9653x over previous
#include <cuda_runtime.h>
#include <cuda_bf16.h>
#include <cstdint>
#include <math.h>

#define D 4096
#define H 2
#define HD (D / H)     // 2048
#define E 8192

#define NSTAGE 7
#define ROW_F4 (D / 4)          // 1024 float4 per 16 KB row
#define ROW_BYTES (D * 4)       // 16384
#define DYN_SMEM (NSTAGE * ROW_BYTES)   // 114688 B

// Scratch (device globals — no allocations allowed). Fully overwritten every run.
__device__ float g_x[2 * D];
__device__ float g_qkv[2 * 3 * D];
__device__ float g_o[2 * D];
__device__ float g_x1[2 * D];
__device__ float g_h[2 * D];
__device__ float g_x2[2 * D];
__device__ float g_g[2 * E];

// ---------------------------------------------------------------------------
// mbarrier / bulk-async helpers
// ---------------------------------------------------------------------------
__device__ __forceinline__ uint32_t smem_u32(const void* p) {
    return (uint32_t)__cvta_generic_to_shared(p);
}
__device__ __forceinline__ void mbar_init(uint32_t addr, uint32_t count) {
    asm volatile("mbarrier.init.shared.b64 [%0], %1;" :: "r"(addr), "r"(count) : "memory");
}
__device__ __forceinline__ void mbar_expect_tx(uint32_t addr, uint32_t bytes) {
    asm volatile("mbarrier.arrive.expect_tx.shared.b64 _, [%0], %1;"
                 :: "r"(addr), "r"(bytes) : "memory");
}
__device__ __forceinline__ void mbar_wait(uint32_t addr, uint32_t parity) {
    asm volatile(
        "{\n\t.reg .pred P;\n\t"
        "WAITL_%=:\n\t"
        "mbarrier.try_wait.parity.acquire.cta.shared::cta.b64 P, [%0], %1, 0x989680;\n\t"
        "@P bra.uni DONEL_%=;\n\t"
        "bra.uni WAITL_%=;\n\t"
        "DONEL_%=:\n\t}"
        :: "r"(addr), "r"(parity) : "memory");
}
__device__ __forceinline__ void bulk_g2s(uint32_t dst_smem, const void* src, uint32_t bytes,
                                         uint32_t mbar) {
    asm volatile(
        "cp.async.bulk.shared::cta.global.mbarrier::complete_tx::bytes [%0], [%1], %2, [%3];"
        :: "r"(dst_smem), "l"(src), "r"(bytes), "r"(mbar) : "memory");
}

// ---------------------------------------------------------------------------
// Stage 0: per-task embeddings
// ---------------------------------------------------------------------------
__global__ void k_embed(const float* __restrict__ ray,
                        const float* __restrict__ w1, const float* __restrict__ b1,
                        const float* __restrict__ w2, const float* __restrict__ b2) {
    int i = blockIdx.x * blockDim.x + threadIdx.x;
    if (i < D) {
        float r0 = __ldg(ray + 0);
        float r1 = __ldg(ray + 1);
        g_x[i]     = fmaxf(r0 * w1[i] + b1[i], 0.0f);
        g_x[D + i] = fmaxf(r1 * w2[i] + b2[i], 0.0f);
    }
}

// ---------------------------------------------------------------------------
// Bulk-async-pipelined 2-row GEMV (K = 4096).
// Each persistent block owns a contiguous span of output rows. Thread 0 keeps
// a 7-deep ring of 16 KB weight rows streaming into shared memory via
// cp.async.bulk + mbarrier (zero register pressure; DMA continues across
// barriers). All 256 threads dot the smem row against x (cached in regs),
// block-reduce, thread 0 writes and immediately refills the stage.
// ---------------------------------------------------------------------------
template <bool RELU, bool RESID>
__global__ void __launch_bounds__(256)
k_gemv_bulk(const float* __restrict__ W,
            const float* __restrict__ b,
            const float* __restrict__ xin,     // [2][D]
            const float* __restrict__ resid,   // [2][N] or null
            float* __restrict__ out,           // [2][N]
            int N) {
    extern __shared__ float4 stg[];            // NSTAGE * ROW_F4 float4
    __shared__ __align__(8) uint64_t mbar[NSTAGE];
    __shared__ float red0[8], red1[8];

    const int tid  = threadIdx.x;
    const int warp = tid >> 5, lane = tid & 31;

    // Contiguous row span for this block.
    const int per = (N + gridDim.x - 1) / gridDim.x;
    const int r0  = blockIdx.x * per;
    const int r1  = min(N, r0 + per);
    const int nrows = r1 - r0;

    // x cached in registers (only operand the RF must hold).
    const float4* __restrict__ x0 = reinterpret_cast<const float4*>(xin);
    const float4* __restrict__ x1 = reinterpret_cast<const float4*>(xin + D);
    float4 xa[4], xb[4];
#pragma unroll
    for (int t = 0; t < 4; ++t) { xa[t] = x0[t * 256 + tid]; xb[t] = x1[t * 256 + tid]; }

    // Init barriers + prologue prefetch.
    if (tid == 0) {
#pragma unroll
        for (int s = 0; s < NSTAGE; ++s) mbar_init(smem_u32(&mbar[s]), 1);
        // fence so the async proxy sees the initialized barriers
        asm volatile("fence.proxy.async.shared::cta;" ::: "memory");
        const int pre = nrows < NSTAGE ? nrows : NSTAGE;
        for (int s = 0; s < pre; ++s) {
            uint32_t mb = smem_u32(&mbar[s]);
            mbar_expect_tx(mb, ROW_BYTES);
            bulk_g2s(smem_u32(&stg[s * ROW_F4]), W + (size_t)(r0 + s) * D, ROW_BYTES, mb);
        }
    }
    __syncthreads();

    for (int k = 0; k < nrows; ++k) {
        const int s  = k % NSTAGE;
        const uint32_t ph = (uint32_t)((k / NSTAGE) & 1);
        const uint32_t mb = smem_u32(&mbar[s]);
        mbar_wait(mb, ph);

        const float4* __restrict__ wrow = &stg[s * ROW_F4];
        float a0 = 0.0f, a1 = 0.0f;
#pragma unroll
        for (int t = 0; t < 4; ++t) {
            float4 w = wrow[t * 256 + tid];
            a0 += w.x * xa[t].x + w.y * xa[t].y + w.z * xa[t].z + w.w * xa[t].w;
            a1 += w.x * xb[t].x + w.y * xb[t].y + w.z * xb[t].z + w.w * xb[t].w;
        }
#pragma unroll
        for (int off = 16; off; off >>= 1) {
            a0 += __shfl_xor_sync(0xFFFFFFFFu, a0, off);
            a1 += __shfl_xor_sync(0xFFFFFFFFu, a1, off);
        }
        if (lane == 0) { red0[warp] = a0; red1[warp] = a1; }
        __syncthreads();   // stage s fully consumed; partials visible

        if (tid == 0) {
            // Refill stage s FIRST (keep DMA busy), then do the epilogue.
            const int kn = k + NSTAGE;
            if (kn < nrows) {
                mbar_expect_tx(mb, ROW_BYTES);
                bulk_g2s(smem_u32(&stg[s * ROW_F4]), W + (size_t)(r0 + kn) * D, ROW_BYTES, mb);
            }
            const int j = r0 + k;
            float s0 = 0.0f, s1 = 0.0f;
#pragma unroll
            for (int w = 0; w < 8; ++w) { s0 += red0[w]; s1 += red1[w]; }
            float bb = b ? b[j] : 0.0f;
            s0 += bb; s1 += bb;
            if (RESID) { s0 += resid[j]; s1 += resid[N + j]; }
            if (RELU)  { s0 = fmaxf(s0, 0.0f); s1 = fmaxf(s1, 0.0f); }
            out[j]     = s0;
            out[N + j] = s1;
        }
        __syncthreads();   // don't let warps re-wait stage s before refill is issued
    }
}

// ---------------------------------------------------------------------------
// Stage 2: multi-head attention on the 2-token sequence (tiny; one block).
// ---------------------------------------------------------------------------
__global__ void k_attn() {
    __shared__ float s_scores[8];
    __shared__ float s_attn[8];
    const int tid = threadIdx.x;
    const int warp = tid >> 5, lane = tid & 31;

    const int h = warp >> 2, l = (warp >> 1) & 1, m = warp & 1;
    const float* __restrict__ q = g_qkv + l * 3 * D + h * HD;
    const float* __restrict__ k = g_qkv + m * 3 * D + D + h * HD;
    float acc = 0.0f;
#pragma unroll 4
    for (int i = lane; i < HD; i += 32) acc += q[i] * k[i];
#pragma unroll
    for (int off = 16; off; off >>= 1) acc += __shfl_xor_sync(0xFFFFFFFFu, acc, off);
    if (lane == 0) s_scores[warp] = acc * rsqrtf((float)HD);
    __syncthreads();

    if (tid < 4) {
        int hh = tid >> 1, ll = tid & 1;
        float s0v = s_scores[hh * 4 + ll * 2 + 0];
        float s1v = s_scores[hh * 4 + ll * 2 + 1];
        float mx = fmaxf(s0v, s1v);
        float e0 = __expf(s0v - mx), e1 = __expf(s1v - mx);
        float inv = 1.0f / (e0 + e1);
        s_attn[hh * 4 + ll * 2 + 0] = e0 * inv;
        s_attn[hh * 4 + ll * 2 + 1] = e1 * inv;
    }
    __syncthreads();

    for (int i = tid; i < 2 * D; i += blockDim.x) {
        int l2 = i / D;
        int d = i - l2 * D;
        int h2 = d / HD;
        float v0 = g_qkv[0 * 3 * D + 2 * D + d];
        float v1 = g_qkv[1 * 3 * D + 2 * D + d];
        g_o[i] = s_attn[h2 * 4 + l2 * 2 + 0] * v0 +
                 s_attn[h2 * 4 + l2 * 2 + 1] * v1;
    }
}

// ---------------------------------------------------------------------------
// Stage 7: out = 0.5 * dot(g0 + g1, exp_w2) + exp_b2
// ---------------------------------------------------------------------------
__global__ void k_final(const float* __restrict__ w2,
                        const float* __restrict__ b2,
                        float* __restrict__ out) {
    __shared__ float red[32];
    float acc = 0.0f;
    for (int i = threadIdx.x; i < E; i += blockDim.x)
        acc += (g_g[i] + g_g[E + i]) * w2[i];
#pragma unroll
    for (int off = 16; off; off >>= 1) acc += __shfl_xor_sync(0xFFFFFFFFu, acc, off);
    const int warp = threadIdx.x >> 5, lane = threadIdx.x & 31;
    if (lane == 0) red[warp] = acc;
    __syncthreads();
    if (threadIdx.x == 0) {
        float s = 0.0f;
        const int nw = blockDim.x >> 5;
        for (int w = 0; w < nw; ++w) s += red[w];
        out[0] = 0.5f * s + b2[0];
    }
}

// ---------------------------------------------------------------------------
extern "C" void kernel_launch(void* const* d_in, const int* in_sizes, int n_in,
                              void* d_out, int out_size) {
    const float* ray        = (const float*)d_in[0];
    const float* emb1_w     = (const float*)d_in[1];
    const float* emb1_b     = (const float*)d_in[2];
    const float* emb2_w     = (const float*)d_in[3];
    const float* emb2_b     = (const float*)d_in[4];
    const float* attn_in_w  = (const float*)d_in[5];
    const float* attn_in_b  = (const float*)d_in[6];
    const float* attn_out_w = (const float*)d_in[7];
    const float* attn_out_b = (const float*)d_in[8];
    const float* ffn1_w     = (const float*)d_in[9];
    const float* ffn1_b     = (const float*)d_in[10];
    const float* ffn2_w     = (const float*)d_in[11];
    const float* ffn2_b     = (const float*)d_in[12];
    const float* exp_w1     = (const float*)d_in[13];
    const float* exp_b1     = (const float*)d_in[14];
    const float* exp_w2     = (const float*)d_in[15];
    const float* exp_b2     = (const float*)d_in[16];
    float* out = (float*)d_out;

    float *px, *pqkv, *po, *px1, *ph, *px2, *pg;
    cudaGetSymbolAddress((void**)&px,   g_x);
    cudaGetSymbolAddress((void**)&pqkv, g_qkv);
    cudaGetSymbolAddress((void**)&po,   g_o);
    cudaGetSymbolAddress((void**)&px1,  g_x1);
    cudaGetSymbolAddress((void**)&ph,   g_h);
    cudaGetSymbolAddress((void**)&px2,  g_x2);
    cudaGetSymbolAddress((void**)&pg,   g_g);

    // Opt-in to large dynamic shared memory (idempotent, cheap).
    static bool attr_done = false;
    if (!attr_done) {
        cudaFuncSetAttribute(k_gemv_bulk<false, false>,
                             cudaFuncAttributeMaxDynamicSharedMemorySize, DYN_SMEM);
        cudaFuncSetAttribute(k_gemv_bulk<false, true>,
                             cudaFuncAttributeMaxDynamicSharedMemorySize, DYN_SMEM);
        cudaFuncSetAttribute(k_gemv_bulk<true, false>,
                             cudaFuncAttributeMaxDynamicSharedMemorySize, DYN_SMEM);
        attr_done = true;
    }

    const int GRID = 148 * 2;   // persistent, 2 blocks/SM (smem-limited)

    // 0: embeddings -> g_x [2][D]
    k_embed<<<(D + 255) / 256, 256>>>(ray, emb1_w, emb1_b, emb2_w, emb2_b);

    // 1: qkv = x @ attn_in_w^T + b  (201 MB)
    k_gemv_bulk<false, false><<<GRID, 256, DYN_SMEM>>>(attn_in_w, attn_in_b, px, nullptr, pqkv, 3 * D);

    // 2: attention -> g_o
    k_attn<<<1, 256>>>();

    // 3: x1 = x + o @ attn_out_w^T + b   (67 MB)
    k_gemv_bulk<false, true><<<GRID, 256, DYN_SMEM>>>(attn_out_w, attn_out_b, po, px, px1, D);

    // 4: h = relu(x1 @ ffn1_w^T + b1)    (67 MB)
    k_gemv_bulk<true, false><<<GRID, 256, DYN_SMEM>>>(ffn1_w, ffn1_b, px1, nullptr, ph, D);

    // 5: x2 = x1 + h @ ffn2_w^T + b2     (67 MB)
    k_gemv_bulk<false, true><<<GRID, 256, DYN_SMEM>>>(ffn2_w, ffn2_b, ph, px1, px2, D);

    // 6: g = relu(x2 @ exp_w1^T + b1)    (134 MB)
    k_gemv_bulk<true, false><<<GRID, 256, DYN_SMEM>>>(exp_w1, exp_b1, px2, nullptr, pg, E);

    // 7: out = mean over seq
    k_final<<<1, 1024>>>(exp_w2, exp_b2, out);
}